// round 13
// baseline (speedup 1.0000x reference)
#include <cuda_runtime.h>
#include <cuda_fp16.h>
#include <cstdint>

#define BB 16
#define LL 256
#define DD 256
#define PP 20

// Device-global scratch (no allocations allowed)
__device__ float g_inv1[BB*LL*PP];
__device__ float g_inv2[BB*LL*PP];
__device__ uint4 g_s2h[BB*LL*DD/8];   // fp16 s2, row-major (8 halfs per uint4)

// ---------------------------------------------------------------------------
// helpers
// ---------------------------------------------------------------------------
__device__ __forceinline__ uint32_t smem_u32(const void* p) {
    uint32_t a;
    asm("{ .reg .u64 t; cvta.to.shared.u64 t, %1; cvt.u32.u64 %0, t; }" : "=r"(a) : "l"(p));
    return a;
}
__device__ __forceinline__ uint32_t pk2h(float x, float y) {
    __half2 t = __floats2half2_rn(x, y);
    return reinterpret_cast<uint32_t&>(t);
}

#define LDSM4(r, addr) \
    asm volatile("ldmatrix.sync.aligned.m8n8.x4.shared.b16 {%0,%1,%2,%3}, [%4];" \
                 : "=r"((r)[0]), "=r"((r)[1]), "=r"((r)[2]), "=r"((r)[3]) : "r"(addr))
#define MMAF16(c, a0, a1, a2, a3, b0, b1) \
    asm volatile("mma.sync.aligned.m16n8k16.row.col.f32.f16.f16.f32 " \
                 "{%0,%1,%2,%3}, {%4,%5,%6,%7}, {%8,%9}, {%0,%1,%2,%3};" \
                 : "+f"((c)[0]), "+f"((c)[1]), "+f"((c)[2]), "+f"((c)[3]) \
                 : "r"(a0), "r"(a1), "r"(a2), "r"(a3), "r"(b0), "r"(b1))
#define CP16(dst, src) \
    asm volatile("cp.async.cg.shared.global [%0], [%1], 16;" :: "r"(dst), "l"(src))
#define CPCOMMIT() asm volatile("cp.async.commit_group;" ::: "memory")
#define CPWAIT0()  asm volatile("cp.async.wait_group 0;" ::: "memory")

// ---------------------------------------------------------------------------
// Kernel 1: inv-norms, shuffle-free, 4-way ILP dot (round-12 version).
// 12 rows/block over unified row space; fuses the s2 -> fp16 conversion.
// ---------------------------------------------------------------------------
#define NR 12
#define WPAD 260
__global__ void __launch_bounds__(256) norms_kernel(const float* __restrict__ s1,
                                                    const float* __restrict__ s2,
                                                    const float* __restrict__ ker) {
    __shared__ float sq[NR][DD];        // 12 KB
    __shared__ float wp[PP*WPAD];       // ~20.3 KB, padded rows

    const int r0  = blockIdx.x * NR;
    const int tid = threadIdx.x;

    #pragma unroll
    for (int j = 0; j < 5; j++) {
        int i = tid + j*256;                 // 0..1279
        int p = i >> 6, d0 = (i & 63) * 4;
        float4 k = ((const float4*)ker)[i];
        *(float4*)&wp[p*WPAD + d0] = make_float4(k.x*k.x, k.y*k.y, k.z*k.z, k.w*k.w);
    }

    for (int i = tid; i < NR*32; i += 256) {
        int row = i >> 5, sg = i & 31;
        int gr = r0 + row;
        int cr = gr < 8192 ? gr : 0;
        const float4* src = (cr < 4096)
            ? (const float4*)(s1 + (size_t)cr*DD + sg*8)
            : (const float4*)(s2 + (size_t)(cr-4096)*DD + sg*8);
        float4 f0 = src[0], f1 = src[1];
        *(float4*)&sq[row][sg*8]     = make_float4(f0.x*f0.x, f0.y*f0.y, f0.z*f0.z, f0.w*f0.w);
        *(float4*)&sq[row][sg*8 + 4] = make_float4(f1.x*f1.x, f1.y*f1.y, f1.z*f1.z, f1.w*f1.w);
        if (gr < 8192 && gr >= 4096)
            g_s2h[(size_t)(gr-4096)*32 + sg] =
                make_uint4(pk2h(f0.x,f0.y), pk2h(f0.z,f0.w),
                           pk2h(f1.x,f1.y), pk2h(f1.z,f1.w));
    }
    __syncthreads();

    if (tid < NR*PP) {
        int row = tid / PP, p = tid % PP;
        int gr = r0 + row;
        if (gr < 8192) {
            const float* sr = sq[row];
            const float* wr = wp + p*WPAD;
            float a0 = 0.f, a1 = 0.f, a2 = 0.f, a3 = 0.f;
            #pragma unroll
            for (int d0 = 0; d0 < DD; d0 += 16) {
                float4 s0 = *(const float4*)(sr + d0);
                float4 w0 = *(const float4*)(wr + d0);
                float4 s1v = *(const float4*)(sr + d0 + 4);
                float4 w1 = *(const float4*)(wr + d0 + 4);
                float4 s2v = *(const float4*)(sr + d0 + 8);
                float4 w2 = *(const float4*)(wr + d0 + 8);
                float4 s3 = *(const float4*)(sr + d0 + 12);
                float4 w3 = *(const float4*)(wr + d0 + 12);
                a0 = fmaf(s0.x, w0.x, a0); a0 = fmaf(s0.y, w0.y, a0);
                a0 = fmaf(s0.z, w0.z, a0); a0 = fmaf(s0.w, w0.w, a0);
                a1 = fmaf(s1v.x, w1.x, a1); a1 = fmaf(s1v.y, w1.y, a1);
                a1 = fmaf(s1v.z, w1.z, a1); a1 = fmaf(s1v.w, w1.w, a1);
                a2 = fmaf(s2v.x, w2.x, a2); a2 = fmaf(s2v.y, w2.y, a2);
                a2 = fmaf(s2v.z, w2.z, a2); a2 = fmaf(s2v.w, w2.w, a2);
                a3 = fmaf(s3.x, w3.x, a3); a3 = fmaf(s3.y, w3.y, a3);
                a3 = fmaf(s3.z, w3.z, a3); a3 = fmaf(s3.w, w3.w, a3);
            }
            float acc = (a0 + a1) + (a2 + a3);
            float inv = rsqrtf(fmaxf(acc, 1e-12f));
            if (gr < 4096) g_inv1[gr*PP + p] = inv;
            else           g_inv2[(gr-4096)*PP + p] = inv;
        }
    }
}

// ---------------------------------------------------------------------------
// smem layout (bytes) — l-tile 64: ~67.3 KB -> 3 CTAs/SM
// ---------------------------------------------------------------------------
#define OFF_A    0          // 64 rows x 512B (fp16, swizzled) = 32768
#define OFF_B    32768      // 2 slots x (128 n-rows x 128B k-quarter) = 32768
#define OFF_W    65536      // 256 f32 = 1024
#define OFF_INV1 66560      // 64 f32 = 256
#define OFF_INV2 66816      // 256 f32 = 1024
#define OFF_RED  67840      // 4 x 64 f32 = 1024
#define SMEM_SZ  68864

__device__ __forceinline__ uint32_t swzA(int row, int seg) {     // 512B rows, seg 0..31
    return (uint32_t)(row*512 + ((seg ^ (row & 7)) << 4));
}

// ---------------------------------------------------------------------------
// Kernel 2: per (b, p, l-quarter) 64x256x256 GEMM, fp16 HMMA, fp32 acc.
// n128 chunks, k-quarter slices (128 rows x 64 k = 16KB), double-buffered.
// Warp grid 2(m) x 4(n); warp tile m32 x n32. Fused row-max epilogue.
// ---------------------------------------------------------------------------
__global__ void __launch_bounds__(256, 3) mpm_mma(const float* __restrict__ s1,
                                                  const float* __restrict__ ker,
                                                  float* __restrict__ out) {
    extern __shared__ char smem[];
    const uint32_t sbase = smem_u32(smem);
    float* w_s    = (float*)(smem + OFF_W);
    float* inv1_s = (float*)(smem + OFF_INV1);
    float* inv2_s = (float*)(smem + OFF_INV2);
    float* red    = (float*)(smem + OFF_RED);

    const int b   = blockIdx.z;
    const int p   = blockIdx.y;
    const int l0  = blockIdx.x * 64;
    const int tid = threadIdx.x;
    const int wid = tid >> 5;
    const int lane = tid & 31;
    const int wm = wid & 1;            // m group (32 rows)
    const int wn = wid >> 1;           // n group (32 cols of 128-chunk)

    const char* s2h_b = (const char*)g_s2h + (size_t)b*LL*DD*2;

    // ---- prefetch slice h into slot h&1: chunk = h>>2 (n128), kq = h&3 ----
    auto prefetch = [&](int h) {
        const int chunk = h >> 2, kq = h & 3;
        const uint32_t dst = sbase + OFF_B + (h & 1)*16384;
        const char* src = s2h_b + (size_t)chunk*128*512 + kq*128;
        #pragma unroll
        for (int j = 0; j < 4; j++) {
            int s = tid + j*256;              // 0..1023: row*8 + seg
            int row = s >> 3, seg = s & 7;
            CP16(dst + row*128 + ((seg ^ (row & 7)) << 4), src + row*512 + seg*16);
        }
    };
    prefetch(0);
    CPCOMMIT();

    // ---- per-p weights + inverse norms ----
    {
        float k = ker[p*DD + tid];             // tid spans 0..255 = D
        w_s[tid] = k*k;
        inv2_s[tid] = g_inv2[((size_t)b*LL + tid)*PP + p];
    }
    if (tid < 64)
        inv1_s[tid] = g_inv1[((size_t)b*LL + l0 + tid)*PP + p] * 0.015625f; // /64
    __syncthreads();

    // ---- build A once: a = fp16(64 * s1 * k^2), 64 rows, swizzled ----
    {
        const float4* s1b = (const float4*)(s1 + ((size_t)b*LL + l0)*DD);
        #pragma unroll 4
        for (int g = tid; g < 64*32; g += 256) {
            int row = g >> 5, grp = g & 31, d0 = grp * 8;
            float4 f0 = s1b[row*64 + grp*2];
            float4 f1 = s1b[row*64 + grp*2 + 1];
            float4 w0 = *(const float4*)(w_s + d0);
            float4 w1 = *(const float4*)(w_s + d0 + 4);
            *(uint4*)(smem + OFF_A + swzA(row, grp)) =
                make_uint4(pk2h(f0.x*w0.x*64.f, f0.y*w0.y*64.f),
                           pk2h(f0.z*w0.z*64.f, f0.w*w0.w*64.f),
                           pk2h(f1.x*w1.x*64.f, f1.y*w1.y*64.f),
                           pk2h(f1.z*w1.z*64.f, f1.w*w1.w*64.f));
        }
    }

    // ---- per-thread ldmatrix bases ----
    const int rx   = lane & 7;
    // A m16k16 x4: row = base + (lane&7) + ((lane>>3)&1)*8 ; k-half = lane>>4
    const int a_row = wm*32 + rx + ((lane >> 3) & 1)*8;
    const uint32_t aA0 = sbase + OFF_A + (uint32_t)a_row*512;          // m-tile 0
    const uint32_t aA1 = aA0 + 16*512;                                  // m-tile 1 (+16 rows)
    const int a_kh = lane >> 4;
    // B n16k16 x4: row(n) = base + (lane&7) + (lane>>4)*8 ; k-half = (lane>>3)&1
    const int b_row0 = wn*32 + rx + (lane >> 4)*8;
    const int b_kh   = (lane >> 3) & 1;

    const float NEG_INF = __int_as_float(0xff800000);
    float mx[2][2] = {{NEG_INF, NEG_INF}, {NEG_INF, NEG_INF}};
    float c[2][4][4];

    for (int h = 0; h < 8; h++) {
        CPWAIT0();
        __syncthreads();               // slot h&1 filled; its previous readers done

        if (h < 7) { prefetch(h + 1); CPCOMMIT(); }

        const uint32_t bS = sbase + OFF_B + (h & 1)*16384;
        const int kbase = (h & 3)*4;   // global k-step base for this quarter

        if ((h & 3) == 0) {
            #pragma unroll
            for (int i = 0; i < 2; i++)
                #pragma unroll
                for (int t = 0; t < 4; t++)
                    #pragma unroll
                    for (int q = 0; q < 4; q++) c[i][t][q] = 0.f;
        }

        #pragma unroll
        for (int ks = 0; ks < 4; ks++) {
            uint32_t a0[4], a1[4];
            const uint32_t aseg = (uint32_t)((((kbase + ks)*2 + a_kh) ^ rx) << 4);
            LDSM4(a0, aA0 + aseg);
            LDSM4(a1, aA1 + aseg);
            const uint32_t bseg = (uint32_t)(((ks*2 + b_kh) ^ rx) << 4);
            #pragma unroll
            for (int g = 0; g < 2; g++) {
                uint32_t bb[4];
                LDSM4(bb, bS + (uint32_t)(b_row0 + g*16)*128 + bseg);
                MMAF16(c[0][g*2  ], a0[0],a0[1],a0[2],a0[3], bb[0], bb[1]);
                MMAF16(c[0][g*2+1], a0[0],a0[1],a0[2],a0[3], bb[2], bb[3]);
                MMAF16(c[1][g*2  ], a1[0],a1[1],a1[2],a1[3], bb[0], bb[1]);
                MMAF16(c[1][g*2+1], a1[0],a1[1],a1[2],a1[3], bb[2], bb[3]);
            }
        }

        if ((h & 3) == 3) {   // chunk complete: fold row-max with per-col inv2
            const int cb = (h >> 2)*128 + wn*32 + (lane & 3)*2;
            #pragma unroll
            for (int t = 0; t < 4; t++) {
                const int col0 = cb + (t >> 1)*16 + (t & 1)*8;
                float iv0 = inv2_s[col0];
                float iv1 = inv2_s[col0 + 1];
                #pragma unroll
                for (int i = 0; i < 2; i++) {
                    mx[i][0] = fmaxf(mx[i][0], fmaxf(c[i][t][0]*iv0, c[i][t][1]*iv1));
                    mx[i][1] = fmaxf(mx[i][1], fmaxf(c[i][t][2]*iv0, c[i][t][3]*iv1));
                }
            }
        }
    }

    // reduce across the 4 lanes sharing each row
    #pragma unroll
    for (int i = 0; i < 2; i++)
        #pragma unroll
        for (int r = 0; r < 2; r++) {
            float v = mx[i][r];
            v = fmaxf(v, __shfl_xor_sync(0xffffffffu, v, 1));
            v = fmaxf(v, __shfl_xor_sync(0xffffffffu, v, 2));
            mx[i][r] = v;
        }

    if ((lane & 3) == 0) {
        int r = lane >> 2;                      // 0..7
        float* rw = red + wn*64 + wm*32;
        rw[r]      = mx[0][0];
        rw[r + 8]  = mx[0][1];
        rw[r + 16] = mx[1][0];
        rw[r + 24] = mx[1][1];
    }
    __syncthreads();

    if (tid < 64) {
        float m = fmaxf(fmaxf(red[tid], red[64 + tid]),
                        fmaxf(red[128 + tid], red[192 + tid])) * inv1_s[tid];
        out[((size_t)b*LL + l0 + tid)*PP + p] = m;
    }
}

// ---------------------------------------------------------------------------
extern "C" void kernel_launch(void* const* d_in, const int* in_sizes, int n_in,
                              void* d_out, int out_size) {
    const float* s1  = (const float*)d_in[0];
    const float* s2  = (const float*)d_in[1];
    const float* ker = (const float*)d_in[2];
    float* out = (float*)d_out;

    cudaFuncSetAttribute(mpm_mma, cudaFuncAttributeMaxDynamicSharedMemorySize, SMEM_SZ);

    norms_kernel<<<(8192 + NR - 1)/NR, 256>>>(s1, s2, ker);
    dim3 grid(4, PP, BB);
    mpm_mma<<<grid, 256, SMEM_SZ>>>(s1, ker, out);
}

// round 14
// speedup vs baseline: 1.0158x; 1.0158x over previous
#include <cuda_runtime.h>
#include <cuda_fp16.h>
#include <cstdint>

#define BB 16
#define LL 256
#define DD 256
#define PP 20

// Device-global scratch (no allocations allowed)
__device__ float g_inv1[BB*LL*PP];
__device__ float g_inv2[BB*LL*PP];
__device__ uint4 g_s2h[BB*LL*DD/8];   // fp16 s2, row-major (8 halfs per uint4)

// ---------------------------------------------------------------------------
// helpers
// ---------------------------------------------------------------------------
__device__ __forceinline__ uint32_t smem_u32(const void* p) {
    uint32_t a;
    asm("{ .reg .u64 t; cvta.to.shared.u64 t, %1; cvt.u32.u64 %0, t; }" : "=r"(a) : "l"(p));
    return a;
}
__device__ __forceinline__ uint32_t pk2h(float x, float y) {
    __half2 t = __floats2half2_rn(x, y);
    return reinterpret_cast<uint32_t&>(t);
}

#define LDSM4(r, addr) \
    asm volatile("ldmatrix.sync.aligned.m8n8.x4.shared.b16 {%0,%1,%2,%3}, [%4];" \
                 : "=r"((r)[0]), "=r"((r)[1]), "=r"((r)[2]), "=r"((r)[3]) : "r"(addr))
#define MMAF16(c, a0, a1, a2, a3, b0, b1) \
    asm volatile("mma.sync.aligned.m16n8k16.row.col.f32.f16.f16.f32 " \
                 "{%0,%1,%2,%3}, {%4,%5,%6,%7}, {%8,%9}, {%0,%1,%2,%3};" \
                 : "+f"((c)[0]), "+f"((c)[1]), "+f"((c)[2]), "+f"((c)[3]) \
                 : "r"(a0), "r"(a1), "r"(a2), "r"(a3), "r"(b0), "r"(b1))
#define CP16(dst, src) \
    asm volatile("cp.async.cg.shared.global [%0], [%1], 16;" :: "r"(dst), "l"(src))
#define CPCOMMIT() asm volatile("cp.async.commit_group;" ::: "memory")
#define CPWAIT0()  asm volatile("cp.async.wait_group 0;" ::: "memory")

// ---------------------------------------------------------------------------
// Kernel 1: inv-norms, shuffle-free, 4-way ILP dot (round-12 version, proven).
// 12 rows/block over unified row space r in [0,8192): r<4096 -> s1 row r,
// else s2 row r-4096. Fuses the s2 -> fp16 conversion.
// ---------------------------------------------------------------------------
#define NR 12
#define WPAD 260
__global__ void __launch_bounds__(256) norms_kernel(const float* __restrict__ s1,
                                                    const float* __restrict__ s2,
                                                    const float* __restrict__ ker) {
    __shared__ float sq[NR][DD];        // 12 KB
    __shared__ float wp[PP*WPAD];       // ~20.3 KB, padded rows

    const int r0  = blockIdx.x * NR;
    const int tid = threadIdx.x;

    #pragma unroll
    for (int j = 0; j < 5; j++) {
        int i = tid + j*256;                 // 0..1279
        int p = i >> 6, d0 = (i & 63) * 4;
        float4 k = ((const float4*)ker)[i];
        *(float4*)&wp[p*WPAD + d0] = make_float4(k.x*k.x, k.y*k.y, k.z*k.z, k.w*k.w);
    }

    for (int i = tid; i < NR*32; i += 256) {
        int row = i >> 5, sg = i & 31;
        int gr = r0 + row;
        int cr = gr < 8192 ? gr : 0;
        const float4* src = (cr < 4096)
            ? (const float4*)(s1 + (size_t)cr*DD + sg*8)
            : (const float4*)(s2 + (size_t)(cr-4096)*DD + sg*8);
        float4 f0 = src[0], f1 = src[1];
        *(float4*)&sq[row][sg*8]     = make_float4(f0.x*f0.x, f0.y*f0.y, f0.z*f0.z, f0.w*f0.w);
        *(float4*)&sq[row][sg*8 + 4] = make_float4(f1.x*f1.x, f1.y*f1.y, f1.z*f1.z, f1.w*f1.w);
        if (gr < 8192 && gr >= 4096)
            g_s2h[(size_t)(gr-4096)*32 + sg] =
                make_uint4(pk2h(f0.x,f0.y), pk2h(f0.z,f0.w),
                           pk2h(f1.x,f1.y), pk2h(f1.z,f1.w));
    }
    __syncthreads();

    if (tid < NR*PP) {
        int row = tid / PP, p = tid % PP;
        int gr = r0 + row;
        if (gr < 8192) {
            const float* sr = sq[row];
            const float* wr = wp + p*WPAD;
            float a0 = 0.f, a1 = 0.f, a2 = 0.f, a3 = 0.f;
            #pragma unroll
            for (int d0 = 0; d0 < DD; d0 += 16) {
                float4 s0 = *(const float4*)(sr + d0);
                float4 w0 = *(const float4*)(wr + d0);
                float4 s1v = *(const float4*)(sr + d0 + 4);
                float4 w1 = *(const float4*)(wr + d0 + 4);
                float4 s2v = *(const float4*)(sr + d0 + 8);
                float4 w2 = *(const float4*)(wr + d0 + 8);
                float4 s3 = *(const float4*)(sr + d0 + 12);
                float4 w3 = *(const float4*)(wr + d0 + 12);
                a0 = fmaf(s0.x, w0.x, a0); a0 = fmaf(s0.y, w0.y, a0);
                a0 = fmaf(s0.z, w0.z, a0); a0 = fmaf(s0.w, w0.w, a0);
                a1 = fmaf(s1v.x, w1.x, a1); a1 = fmaf(s1v.y, w1.y, a1);
                a1 = fmaf(s1v.z, w1.z, a1); a1 = fmaf(s1v.w, w1.w, a1);
                a2 = fmaf(s2v.x, w2.x, a2); a2 = fmaf(s2v.y, w2.y, a2);
                a2 = fmaf(s2v.z, w2.z, a2); a2 = fmaf(s2v.w, w2.w, a2);
                a3 = fmaf(s3.x, w3.x, a3); a3 = fmaf(s3.y, w3.y, a3);
                a3 = fmaf(s3.z, w3.z, a3); a3 = fmaf(s3.w, w3.w, a3);
            }
            float acc = (a0 + a1) + (a2 + a3);
            float inv = rsqrtf(fmaxf(acc, 1e-12f));
            if (gr < 4096) g_inv1[gr*PP + p] = inv;
            else           g_inv2[(gr-4096)*PP + p] = inv;
        }
    }
}

// ---------------------------------------------------------------------------
// smem layout (bytes) — round-11 main kernel (proven best: 43.2 us)
// ---------------------------------------------------------------------------
#define OFF_A    0          // 128 rows x 512B (fp16, swizzled) = 65536
#define OFF_B    65536      // 2 slots x (128 n-rows x 128B k-quarter) = 32768
#define OFF_W    98304      // 256 f32
#define OFF_INV1 99328      // 128 f32
#define OFF_INV2 99840      // 256 f32
#define OFF_RED  100864     // 2 x 128 f32
#define SMEM_SZ  101888

__device__ __forceinline__ uint32_t swzA(int row, int seg) {     // 512B rows, seg 0..31
    return (uint32_t)(row*512 + ((seg ^ (row & 7)) << 4));
}

// ---------------------------------------------------------------------------
// Kernel 2: per (b, p, l-half) 128x256x256 GEMM, fp16 HMMA, fp32 acc.
// n128 chunks, k-quarter slices (128 rows x 64 k = 16KB), double-buffered.
// Warp grid 4(m) x 2(n); warp tile m32 x n64. Fused row-max epilogue.
// ---------------------------------------------------------------------------
__global__ void __launch_bounds__(256, 2) mpm_mma(const float* __restrict__ s1,
                                                  const float* __restrict__ ker,
                                                  float* __restrict__ out) {
    extern __shared__ char smem[];
    const uint32_t sbase = smem_u32(smem);
    float* w_s    = (float*)(smem + OFF_W);
    float* inv1_s = (float*)(smem + OFF_INV1);
    float* inv2_s = (float*)(smem + OFF_INV2);
    float* red    = (float*)(smem + OFF_RED);

    const int b   = blockIdx.z;
    const int p   = blockIdx.y;
    const int l0  = blockIdx.x * 128;
    const int tid = threadIdx.x;
    const int wid = tid >> 5;
    const int lane = tid & 31;
    const int wm = wid & 3;            // m group (32 rows)
    const int wn = wid >> 2;           // n group (64 cols of 128-chunk)

    const char* s2h_b = (const char*)g_s2h + (size_t)b*LL*DD*2;

    // ---- prefetch slice h into slot h&1: chunk = h>>2 (n128), kq = h&3 ----
    auto prefetch = [&](int h) {
        const int chunk = h >> 2, kq = h & 3;
        const uint32_t dst = sbase + OFF_B + (h & 1)*16384;
        const char* src = s2h_b + (size_t)chunk*128*512 + kq*128;
        #pragma unroll
        for (int j = 0; j < 4; j++) {
            int s = tid + j*256;              // 0..1023: row*8 + seg
            int row = s >> 3, seg = s & 7;
            CP16(dst + row*128 + ((seg ^ (row & 7)) << 4), src + row*512 + seg*16);
        }
    };
    prefetch(0);
    CPCOMMIT();

    // ---- per-p weights + inverse norms ----
    {
        float k = ker[p*DD + tid];             // tid spans 0..255 = D
        w_s[tid] = k*k;
        inv2_s[tid] = g_inv2[((size_t)b*LL + tid)*PP + p];
    }
    if (tid < 128)
        inv1_s[tid] = g_inv1[((size_t)b*LL + l0 + tid)*PP + p] * 0.015625f; // /64
    __syncthreads();

    // ---- build A once: a = fp16(64 * s1 * k^2), 512B rows, swizzled ----
    {
        const float4* s1b = (const float4*)(s1 + ((size_t)b*LL + l0)*DD);
        #pragma unroll 4
        for (int g = tid; g < 128*32; g += 256) {
            int row = g >> 5, grp = g & 31, d0 = grp * 8;
            float4 f0 = s1b[row*64 + grp*2];
            float4 f1 = s1b[row*64 + grp*2 + 1];
            float4 w0 = *(const float4*)(w_s + d0);
            float4 w1 = *(const float4*)(w_s + d0 + 4);
            *(uint4*)(smem + OFF_A + swzA(row, grp)) =
                make_uint4(pk2h(f0.x*w0.x*64.f, f0.y*w0.y*64.f),
                           pk2h(f0.z*w0.z*64.f, f0.w*w0.w*64.f),
                           pk2h(f1.x*w1.x*64.f, f1.y*w1.y*64.f),
                           pk2h(f1.z*w1.z*64.f, f1.w*w1.w*64.f));
        }
    }

    // ---- per-thread ldmatrix bases ----
    const int rx   = lane & 7;
    // A m16k16 x4: row = base + (lane&7) + ((lane>>3)&1)*8 ; k-half = lane>>4
    const int a_row = wm*32 + rx + ((lane >> 3) & 1)*8;
    const uint32_t aA0 = sbase + OFF_A + (uint32_t)a_row*512;          // m-tile 0
    const uint32_t aA1 = aA0 + 16*512;                                  // m-tile 1 (+16 rows)
    const int a_kh = lane >> 4;
    // B n16k16 x4: row(n) = base + (lane&7) + (lane>>4)*8 ; k-half = (lane>>3)&1
    const int b_row0 = wn*64 + rx + (lane >> 4)*8;
    const int b_kh   = (lane >> 3) & 1;

    const float NEG_INF = __int_as_float(0xff800000);
    float mx[2][2] = {{NEG_INF, NEG_INF}, {NEG_INF, NEG_INF}};
    float c[2][8][4];

    for (int h = 0; h < 8; h++) {
        CPWAIT0();
        __syncthreads();               // slot h&1 filled; its previous readers done

        if (h < 7) { prefetch(h + 1); CPCOMMIT(); }

        const uint32_t bS = sbase + OFF_B + (h & 1)*16384;
        const int kbase = (h & 3)*4;   // global k-step base for this quarter

        if ((h & 3) == 0) {
            #pragma unroll
            for (int i = 0; i < 2; i++)
                #pragma unroll
                for (int t = 0; t < 8; t++)
                    #pragma unroll
                    for (int q = 0; q < 4; q++) c[i][t][q] = 0.f;
        }

        #pragma unroll
        for (int ks = 0; ks < 4; ks++) {
            uint32_t a0[4], a1[4];
            const uint32_t aseg = (uint32_t)((((kbase + ks)*2 + a_kh) ^ rx) << 4);
            LDSM4(a0, aA0 + aseg);
            LDSM4(a1, aA1 + aseg);
            const uint32_t bseg = (uint32_t)(((ks*2 + b_kh) ^ rx) << 4);
            #pragma unroll
            for (int g = 0; g < 4; g++) {
                uint32_t bb[4];
                LDSM4(bb, bS + (uint32_t)(b_row0 + g*16)*128 + bseg);
                MMAF16(c[0][g*2  ], a0[0],a0[1],a0[2],a0[3], bb[0], bb[1]);
                MMAF16(c[0][g*2+1], a0[0],a0[1],a0[2],a0[3], bb[2], bb[3]);
                MMAF16(c[1][g*2  ], a1[0],a1[1],a1[2],a1[3], bb[0], bb[1]);
                MMAF16(c[1][g*2+1], a1[0],a1[1],a1[2],a1[3], bb[2], bb[3]);
            }
        }

        if ((h & 3) == 3) {   // chunk complete: fold row-max with per-col inv2
            const int cb = (h >> 2)*128 + wn*64 + (lane & 3)*2;
            #pragma unroll
            for (int t = 0; t < 8; t++) {
                const int col0 = cb + (t >> 1)*16 + (t & 1)*8;
                float iv0 = inv2_s[col0];
                float iv1 = inv2_s[col0 + 1];
                #pragma unroll
                for (int i = 0; i < 2; i++) {
                    mx[i][0] = fmaxf(mx[i][0], fmaxf(c[i][t][0]*iv0, c[i][t][1]*iv1));
                    mx[i][1] = fmaxf(mx[i][1], fmaxf(c[i][t][2]*iv0, c[i][t][3]*iv1));
                }
            }
        }
    }

    // reduce across the 4 lanes sharing each row
    #pragma unroll
    for (int i = 0; i < 2; i++)
        #pragma unroll
        for (int r = 0; r < 2; r++) {
            float v = mx[i][r];
            v = fmaxf(v, __shfl_xor_sync(0xffffffffu, v, 1));
            v = fmaxf(v, __shfl_xor_sync(0xffffffffu, v, 2));
            mx[i][r] = v;
        }

    if ((lane & 3) == 0) {
        int r = lane >> 2;                      // 0..7
        float* rw = red + wn*128 + wm*32;
        rw[r]      = mx[0][0];
        rw[r + 8]  = mx[0][1];
        rw[r + 16] = mx[1][0];
        rw[r + 24] = mx[1][1];
    }
    __syncthreads();

    if (tid < 128) {
        float m = fmaxf(red[tid], red[128 + tid]) * inv1_s[tid];
        out[((size_t)b*LL + l0 + tid)*PP + p] = m;
    }
}

// ---------------------------------------------------------------------------
extern "C" void kernel_launch(void* const* d_in, const int* in_sizes, int n_in,
                              void* d_out, int out_size) {
    const float* s1  = (const float*)d_in[0];
    const float* s2  = (const float*)d_in[1];
    const float* ker = (const float*)d_in[2];
    float* out = (float*)d_out;

    cudaFuncSetAttribute(mpm_mma, cudaFuncAttributeMaxDynamicSharedMemorySize, SMEM_SZ);

    norms_kernel<<<(8192 + NR - 1)/NR, 256>>>(s1, s2, ker);
    dim3 grid(2, PP, BB);
    mpm_mma<<<grid, 256, SMEM_SZ>>>(s1, ker, out);
}

// round 16
// speedup vs baseline: 1.0715x; 1.0548x over previous
#include <cuda_runtime.h>
#include <cuda_fp16.h>
#include <cstdint>

#define BB 16
#define LL 256
#define DD 256
#define PP 20

// Device-global scratch (no allocations allowed)
__device__ float g_inv1[BB*LL*PP];
__device__ float g_inv2[BB*LL*PP];
__device__ uint4 g_s2h[BB*LL*DD/8];   // fp16 s2, row-major (8 halfs per uint4)

// ---------------------------------------------------------------------------
// helpers
// ---------------------------------------------------------------------------
__device__ __forceinline__ uint32_t smem_u32(const void* p) {
    uint32_t a;
    asm("{ .reg .u64 t; cvta.to.shared.u64 t, %1; cvt.u32.u64 %0, t; }" : "=r"(a) : "l"(p));
    return a;
}
__device__ __forceinline__ uint32_t pk2h(float x, float y) {
    __half2 t = __floats2half2_rn(x, y);
    return reinterpret_cast<uint32_t&>(t);
}

#define LDSM4(r, addr) \
    asm volatile("ldmatrix.sync.aligned.m8n8.x4.shared.b16 {%0,%1,%2,%3}, [%4];" \
                 : "=r"((r)[0]), "=r"((r)[1]), "=r"((r)[2]), "=r"((r)[3]) : "r"(addr))
#define MMAF16(c, a0, a1, a2, a3, b0, b1) \
    asm volatile("mma.sync.aligned.m16n8k16.row.col.f32.f16.f16.f32 " \
                 "{%0,%1,%2,%3}, {%4,%5,%6,%7}, {%8,%9}, {%0,%1,%2,%3};" \
                 : "+f"((c)[0]), "+f"((c)[1]), "+f"((c)[2]), "+f"((c)[3]) \
                 : "r"(a0), "r"(a1), "r"(a2), "r"(a3), "r"(b0), "r"(b1))
#define CP16(dst, src) \
    asm volatile("cp.async.cg.shared.global [%0], [%1], 16;" :: "r"(dst), "l"(src))
#define CPCOMMIT() asm volatile("cp.async.commit_group;" ::: "memory")
#define CPWAIT0()  asm volatile("cp.async.wait_group 0;" ::: "memory")

// ---------------------------------------------------------------------------
// Kernel 1: inv-norms, shuffle-free, 4-way ILP dot (proven). 12 rows/block
// over unified row space; fuses the s2 -> fp16 conversion.
// ---------------------------------------------------------------------------
#define NR 12
#define WPAD 260
__global__ void __launch_bounds__(256) norms_kernel(const float* __restrict__ s1,
                                                    const float* __restrict__ s2,
                                                    const float* __restrict__ ker) {
    __shared__ float sq[NR][DD];        // 12 KB
    __shared__ float wp[PP*WPAD];       // ~20.3 KB, padded rows

    const int r0  = blockIdx.x * NR;
    const int tid = threadIdx.x;

    #pragma unroll
    for (int j = 0; j < 5; j++) {
        int i = tid + j*256;                 // 0..1279
        int p = i >> 6, d0 = (i & 63) * 4;
        float4 k = ((const float4*)ker)[i];
        *(float4*)&wp[p*WPAD + d0] = make_float4(k.x*k.x, k.y*k.y, k.z*k.z, k.w*k.w);
    }

    for (int i = tid; i < NR*32; i += 256) {
        int row = i >> 5, sg = i & 31;
        int gr = r0 + row;
        int cr = gr < 8192 ? gr : 0;
        const float4* src = (cr < 4096)
            ? (const float4*)(s1 + (size_t)cr*DD + sg*8)
            : (const float4*)(s2 + (size_t)(cr-4096)*DD + sg*8);
        float4 f0 = src[0], f1 = src[1];
        *(float4*)&sq[row][sg*8]     = make_float4(f0.x*f0.x, f0.y*f0.y, f0.z*f0.z, f0.w*f0.w);
        *(float4*)&sq[row][sg*8 + 4] = make_float4(f1.x*f1.x, f1.y*f1.y, f1.z*f1.z, f1.w*f1.w);
        if (gr < 8192 && gr >= 4096)
            g_s2h[(size_t)(gr-4096)*32 + sg] =
                make_uint4(pk2h(f0.x,f0.y), pk2h(f0.z,f0.w),
                           pk2h(f1.x,f1.y), pk2h(f1.z,f1.w));
    }
    __syncthreads();

    if (tid < NR*PP) {
        int row = tid / PP, p = tid % PP;
        int gr = r0 + row;
        if (gr < 8192) {
            const float* sr = sq[row];
            const float* wr = wp + p*WPAD;
            float a0 = 0.f, a1 = 0.f, a2 = 0.f, a3 = 0.f;
            #pragma unroll
            for (int d0 = 0; d0 < DD; d0 += 16) {
                float4 s0 = *(const float4*)(sr + d0);
                float4 w0 = *(const float4*)(wr + d0);
                float4 s1v = *(const float4*)(sr + d0 + 4);
                float4 w1 = *(const float4*)(wr + d0 + 4);
                float4 s2v = *(const float4*)(sr + d0 + 8);
                float4 w2 = *(const float4*)(wr + d0 + 8);
                float4 s3 = *(const float4*)(sr + d0 + 12);
                float4 w3 = *(const float4*)(wr + d0 + 12);
                a0 = fmaf(s0.x, w0.x, a0); a0 = fmaf(s0.y, w0.y, a0);
                a0 = fmaf(s0.z, w0.z, a0); a0 = fmaf(s0.w, w0.w, a0);
                a1 = fmaf(s1v.x, w1.x, a1); a1 = fmaf(s1v.y, w1.y, a1);
                a1 = fmaf(s1v.z, w1.z, a1); a1 = fmaf(s1v.w, w1.w, a1);
                a2 = fmaf(s2v.x, w2.x, a2); a2 = fmaf(s2v.y, w2.y, a2);
                a2 = fmaf(s2v.z, w2.z, a2); a2 = fmaf(s2v.w, w2.w, a2);
                a3 = fmaf(s3.x, w3.x, a3); a3 = fmaf(s3.y, w3.y, a3);
                a3 = fmaf(s3.z, w3.z, a3); a3 = fmaf(s3.w, w3.w, a3);
            }
            float acc = (a0 + a1) + (a2 + a3);
            float inv = rsqrtf(fmaxf(acc, 1e-12f));
            if (gr < 4096) g_inv1[gr*PP + p] = inv;
            else           g_inv2[(gr-4096)*PP + p] = inv;
        }
    }
}

// ---------------------------------------------------------------------------
// smem layout (bytes) — l-tile 64, 128-thread CTA: ~68 KB -> 3 CTAs/SM
// ---------------------------------------------------------------------------
#define OFF_A    0          // 64 rows x 512B (fp16, swizzled) = 32768
#define OFF_B    32768      // 2 slots x (128 n-rows x 128B k-quarter) = 32768
#define OFF_W    65536      // 256 f32 = 1024
#define OFF_INV1 66560      // 64 f32 = 256
#define OFF_INV2 66816      // 256 f32 = 1024
#define OFF_RED  67840      // 2 x 64 f32 = 512
#define SMEM_SZ  68352

__device__ __forceinline__ uint32_t swzA(int row, int seg) {     // 512B rows, seg 0..31
    return (uint32_t)(row*512 + ((seg ^ (row & 7)) << 4));
}

// ---------------------------------------------------------------------------
// Kernel 2: per (b, p, l-quarter) 64x256x256 GEMM, fp16 HMMA, fp32 acc.
// 128 threads, warp grid 2(m) x 2(n), warp tile m32 x n64 — per-warp inner
// loop identical to the proven round-11 kernel. n128 chunks, k-quarter
// slices (16KB), double-buffered. Fused row-max epilogue.
// ---------------------------------------------------------------------------
__global__ void __launch_bounds__(128, 3) mpm_mma(const float* __restrict__ s1,
                                                  const float* __restrict__ ker,
                                                  float* __restrict__ out) {
    extern __shared__ char smem[];
    const uint32_t sbase = smem_u32(smem);
    float* w_s    = (float*)(smem + OFF_W);
    float* inv1_s = (float*)(smem + OFF_INV1);
    float* inv2_s = (float*)(smem + OFF_INV2);
    float* red    = (float*)(smem + OFF_RED);

    const int b   = blockIdx.z;
    const int p   = blockIdx.y;
    const int l0  = blockIdx.x * 64;
    const int tid = threadIdx.x;
    const int wid = tid >> 5;
    const int lane = tid & 31;
    const int wm = wid & 1;            // m group (32 rows)
    const int wn = wid >> 1;           // n group (64 cols of 128-chunk)

    const char* s2h_b = (const char*)g_s2h + (size_t)b*LL*DD*2;

    // ---- prefetch slice h into slot h&1: chunk = h>>2 (n128), kq = h&3 ----
    auto prefetch = [&](int h) {
        const int chunk = h >> 2, kq = h & 3;
        const uint32_t dst = sbase + OFF_B + (h & 1)*16384;
        const char* src = s2h_b + (size_t)chunk*128*512 + kq*128;
        #pragma unroll
        for (int j = 0; j < 8; j++) {
            int s = tid + j*128;              // 0..1023: row*8 + seg
            int row = s >> 3, seg = s & 7;
            CP16(dst + row*128 + ((seg ^ (row & 7)) << 4), src + row*512 + seg*16);
        }
    };
    prefetch(0);
    CPCOMMIT();

    // ---- per-p weights + inverse norms ----
    #pragma unroll
    for (int j = 0; j < 2; j++) {
        int d = tid + j*128;                   // 0..255 = D
        float k = ker[p*DD + d];
        w_s[d] = k*k;
        inv2_s[d] = g_inv2[((size_t)b*LL + d)*PP + p];
    }
    if (tid < 64)
        inv1_s[tid] = g_inv1[((size_t)b*LL + l0 + tid)*PP + p] * 0.015625f; // /64
    __syncthreads();

    // ---- build A once: a = fp16(64 * s1 * k^2), 64 rows, swizzled ----
    {
        const float4* s1b = (const float4*)(s1 + ((size_t)b*LL + l0)*DD);
        #pragma unroll 4
        for (int g = tid; g < 64*32; g += 128) {
            int row = g >> 5, grp = g & 31, d0 = grp * 8;
            float4 f0 = s1b[row*64 + grp*2];
            float4 f1 = s1b[row*64 + grp*2 + 1];
            float4 w0 = *(const float4*)(w_s + d0);
            float4 w1 = *(const float4*)(w_s + d0 + 4);
            *(uint4*)(smem + OFF_A + swzA(row, grp)) =
                make_uint4(pk2h(f0.x*w0.x*64.f, f0.y*w0.y*64.f),
                           pk2h(f0.z*w0.z*64.f, f0.w*w0.w*64.f),
                           pk2h(f1.x*w1.x*64.f, f1.y*w1.y*64.f),
                           pk2h(f1.z*w1.z*64.f, f1.w*w1.w*64.f));
        }
    }

    // ---- per-thread ldmatrix bases ----
    const int rx   = lane & 7;
    // A m16k16 x4: row = base + (lane&7) + ((lane>>3)&1)*8 ; k-half = lane>>4
    const int a_row = wm*32 + rx + ((lane >> 3) & 1)*8;
    const uint32_t aA0 = sbase + OFF_A + (uint32_t)a_row*512;          // m-tile 0
    const uint32_t aA1 = aA0 + 16*512;                                  // m-tile 1 (+16 rows)
    const int a_kh = lane >> 4;
    // B n16k16 x4: row(n) = base + (lane&7) + (lane>>4)*8 ; k-half = (lane>>3)&1
    const int b_row0 = wn*64 + rx + (lane >> 4)*8;
    const int b_kh   = (lane >> 3) & 1;

    const float NEG_INF = __int_as_float(0xff800000);
    float mx[2][2] = {{NEG_INF, NEG_INF}, {NEG_INF, NEG_INF}};
    float c[2][8][4];

    for (int h = 0; h < 8; h++) {
        CPWAIT0();
        __syncthreads();               // slot h&1 filled; its previous readers done

        if (h < 7) { prefetch(h + 1); CPCOMMIT(); }

        const uint32_t bS = sbase + OFF_B + (h & 1)*16384;
        const int kbase = (h & 3)*4;   // global k-step base for this quarter

        if ((h & 3) == 0) {
            #pragma unroll
            for (int i = 0; i < 2; i++)
                #pragma unroll
                for (int t = 0; t < 8; t++)
                    #pragma unroll
                    for (int q = 0; q < 4; q++) c[i][t][q] = 0.f;
        }

        #pragma unroll
        for (int ks = 0; ks < 4; ks++) {
            uint32_t a0[4], a1[4];
            const uint32_t aseg = (uint32_t)((((kbase + ks)*2 + a_kh) ^ rx) << 4);
            LDSM4(a0, aA0 + aseg);
            LDSM4(a1, aA1 + aseg);
            const uint32_t bseg = (uint32_t)(((ks*2 + b_kh) ^ rx) << 4);
            #pragma unroll
            for (int g = 0; g < 4; g++) {
                uint32_t bb[4];
                LDSM4(bb, bS + (uint32_t)(b_row0 + g*16)*128 + bseg);
                MMAF16(c[0][g*2  ], a0[0],a0[1],a0[2],a0[3], bb[0], bb[1]);
                MMAF16(c[0][g*2+1], a0[0],a0[1],a0[2],a0[3], bb[2], bb[3]);
                MMAF16(c[1][g*2  ], a1[0],a1[1],a1[2],a1[3], bb[0], bb[1]);
                MMAF16(c[1][g*2+1], a1[0],a1[1],a1[2],a1[3], bb[2], bb[3]);
            }
        }

        if ((h & 3) == 3) {   // chunk complete: fold row-max with per-col inv2
            const int cb = (h >> 2)*128 + wn*64 + (lane & 3)*2;
            #pragma unroll
            for (int t = 0; t < 8; t++) {
                const int col0 = cb + (t >> 1)*16 + (t & 1)*8;
                float iv0 = inv2_s[col0];
                float iv1 = inv2_s[col0 + 1];
                #pragma unroll
                for (int i = 0; i < 2; i++) {
                    mx[i][0] = fmaxf(mx[i][0], fmaxf(c[i][t][0]*iv0, c[i][t][1]*iv1));
                    mx[i][1] = fmaxf(mx[i][1], fmaxf(c[i][t][2]*iv0, c[i][t][3]*iv1));
                }
            }
        }
    }

    // reduce across the 4 lanes sharing each row
    #pragma unroll
    for (int i = 0; i < 2; i++)
        #pragma unroll
        for (int r = 0; r < 2; r++) {
            float v = mx[i][r];
            v = fmaxf(v, __shfl_xor_sync(0xffffffffu, v, 1));
            v = fmaxf(v, __shfl_xor_sync(0xffffffffu, v, 2));
            mx[i][r] = v;
        }

    if ((lane & 3) == 0) {
        int r = lane >> 2;                      // 0..7
        float* rw = red + wn*64 + wm*32;
        rw[r]      = mx[0][0];
        rw[r + 8]  = mx[0][1];
        rw[r + 16] = mx[1][0];
        rw[r + 24] = mx[1][1];
    }
    __syncthreads();

    if (tid < 64) {
        float m = fmaxf(red[tid], red[64 + tid]) * inv1_s[tid];
        out[((size_t)b*LL + l0 + tid)*PP + p] = m;
    }
}

// ---------------------------------------------------------------------------
extern "C" void kernel_launch(void* const* d_in, const int* in_sizes, int n_in,
                              void* d_out, int out_size) {
    const float* s1  = (const float*)d_in[0];
    const float* s2  = (const float*)d_in[1];
    const float* ker = (const float*)d_in[2];
    float* out = (float*)d_out;

    cudaFuncSetAttribute(mpm_mma, cudaFuncAttributeMaxDynamicSharedMemorySize, SMEM_SZ);

    norms_kernel<<<(8192 + NR - 1)/NR, 256>>>(s1, s2, ker);
    dim3 grid(4, PP, BB);
    mpm_mma<<<grid, 128, SMEM_SZ>>>(s1, ker, out);
}